// round 8
// baseline (speedup 1.0000x reference)
#include <cuda_runtime.h>
#include <math.h>

#define NEG_INF_VAL -10000000000.0f

namespace {
constexpr int Hc = 512;
constexpr int Sc = 1024;
constexpr int KS = 8;          // split-K for H=512 GEMMs
constexpr int SLICES = 16;     // attn slices per beam
constexpr int NPART = 64 * SLICES;  // 1024

// float scratch offsets
constexpr int OFF_GIP     = 0;                          // KS*64*1536
constexpr int OFF_GHP     = OFF_GIP + KS * 64 * 1536;
constexpr int OFF_QP      = OFF_GHP + KS * 64 * 1536;   // 64*512 (atomic-accumulated)
constexpr int OFF_HNEW    = OFF_QP + 64 * 512;
constexpr int OFF_QB1     = OFF_HNEW + 64 * 512;
constexpr int OFF_ATTN    = OFF_QB1 + 64;               // 64x1024
constexpr int OFF_PARTM   = OFF_ATTN + 64 * 1024;
constexpr int OFF_PARTL   = OFF_PARTM + NPART;
constexpr int OFF_PARTACC = OFF_PARTL + NPART;          // 1024*512
constexpr int OFF_CTXRAW  = OFF_PARTACC + NPART * 512;
constexpr int OFF_CTX     = OFF_CTXRAW + 64 * 512;
constexpr int OFF_RESULT  = OFF_CTX + 64 * 512;
constexpr int OFF_TKLOG   = OFF_RESULT + 64 * 512;
constexpr int SCR_TOTAL   = OFF_TKLOG + 256;

// output layout (floats), tuple members concatenated in order
constexpr int O_RESULT = 0;
constexpr int O_HIDDEN = 32768;
constexpr int O_IDX    = 65536;
constexpr int O_ATTNS  = 65792;
constexpr int O_MASK   = 327936;
constexpr int O_SCORES = 393472;
}

__device__ __align__(16) float g_scr[SCR_TOTAL];
__device__ int g_tkidx[256];
__device__ unsigned g_barcnt[8];   // monotonic ticket counters (never reset)

// ---------------- software grid barrier (co-resident grids only) ----------------
__device__ __forceinline__ void gridbar(int id, unsigned nb) {
    __syncthreads();
    if (threadIdx.x == 0) {
        __threadfence();
        unsigned ticket = atomicAdd(&g_barcnt[id], 1u);
        unsigned target = ticket - (ticket % nb) + nb;
        while (__ldcg((const unsigned*)&g_barcnt[id]) < target) __nanosleep(32);
        __threadfence();
    }
    __syncthreads();
}

// ---------------- GEMM tiles (64 rows x 64 cols, K-chunk = ITERS*32) ----------------
// LDCGA: read A via __ldcg (A written earlier in SAME kernel by other blocks)
template<int ITERS, bool ATOMIC, bool LDCGA>
__device__ __forceinline__ void gemm_bt_tile(const float* __restrict__ A, int lda,
                                             const float* __restrict__ B, int ldb,
                                             float* __restrict__ C, int ldc,
                                             const float* __restrict__ bias, bool addBias,
                                             int j0, int k0,
                                             float (*As)[65], float (*Bs)[65]) {
    const int t = threadIdx.x;
    const int bx = (t & 15) * 4;
    const int by = (t >> 4) * 4;
    float acc[4][4] = {};
#pragma unroll
    for (int it = 0; it < ITERS; it++) {
        const int kk = k0 + it * 32;
#pragma unroll
        for (int i = 0; i < 8; i++) {
            int idx = t + i * 256;
            int r = idx >> 5, c = idx & 31;
            As[c][r] = LDCGA ? __ldcg(&A[r * lda + kk + c]) : A[r * lda + kk + c];
            Bs[c][r] = B[(j0 + r) * ldb + kk + c];
        }
        __syncthreads();
#pragma unroll
        for (int c = 0; c < 32; c++) {
            float b0 = Bs[c][bx + 0], b1 = Bs[c][bx + 1], b2 = Bs[c][bx + 2], b3 = Bs[c][bx + 3];
#pragma unroll
            for (int r = 0; r < 4; r++) {
                float av = As[c][by + r];
                acc[r][0] += av * b0; acc[r][1] += av * b1;
                acc[r][2] += av * b2; acc[r][3] += av * b3;
            }
        }
        __syncthreads();
    }
#pragma unroll
    for (int r = 0; r < 4; r++)
#pragma unroll
        for (int cc = 0; cc < 4; cc++) {
            float v = acc[r][cc];
            if (addBias) v += bias[j0 + bx + cc];
            if (ATOMIC) atomicAdd(&C[(by + r) * ldc + j0 + bx + cc], v);
            else        C[(by + r) * ldc + j0 + bx + cc] = v;
        }
}

template<int ITERS, bool ATOMIC, bool LDCGA>
__device__ __forceinline__ void gemm_ab_tile(const float* __restrict__ A, int lda,
                                             const float* __restrict__ B, int ldb,
                                             float* __restrict__ C, int ldc,
                                             int j0, int k0,
                                             float (*As)[65], float (*Bs)[65]) {
    const int t = threadIdx.x;
    const int bx = (t & 15) * 4;
    const int by = (t >> 4) * 4;
    float acc[4][4] = {};
#pragma unroll
    for (int it = 0; it < ITERS; it++) {
        const int kk = k0 + it * 32;
#pragma unroll
        for (int i = 0; i < 8; i++) {
            int idx = t + i * 256;
            int r = idx >> 5, c = idx & 31;
            As[c][r] = LDCGA ? __ldcg(&A[r * lda + kk + c]) : A[r * lda + kk + c];
        }
#pragma unroll
        for (int i = 0; i < 8; i++) {
            int idx = t + i * 256;
            int c = idx >> 6, jj = idx & 63;
            Bs[c][jj] = B[(kk + c) * ldb + j0 + jj];
        }
        __syncthreads();
#pragma unroll
        for (int c = 0; c < 32; c++) {
            float b0 = Bs[c][bx + 0], b1 = Bs[c][bx + 1], b2 = Bs[c][bx + 2], b3 = Bs[c][bx + 3];
#pragma unroll
            for (int r = 0; r < 4; r++) {
                float av = As[c][by + r];
                acc[r][0] += av * b0; acc[r][1] += av * b1;
                acc[r][2] += av * b2; acc[r][3] += av * b3;
            }
        }
        __syncthreads();
    }
#pragma unroll
    for (int r = 0; r < 4; r++)
#pragma unroll
        for (int cc = 0; cc < 4; cc++) {
            if (ATOMIC) atomicAdd(&C[(by + r) * ldc + j0 + bx + cc], acc[r][cc]);
            else        C[(by + r) * ldc + j0 + bx + cc] = acc[r][cc];
        }
}

// ---- gi/gh partials: grid (24, KS, 2), block 256 ----
__global__ void __launch_bounds__(256) k_gru(const float* __restrict__ x, const float* __restrict__ h,
                                             const float* __restrict__ wih, const float* __restrict__ whh) {
    __shared__ float As[32][65];
    __shared__ float Bs[32][65];
    const float* A = blockIdx.z ? h : x;
    const float* B = blockIdx.z ? whh : wih;
    float* C = g_scr + (blockIdx.z ? OFF_GHP : OFF_GIP) + blockIdx.y * (64 * 1536);
    gemm_bt_tile<2, false, false>(A, Hc, B, Hc, C, 1536, nullptr, false,
                                  blockIdx.x * 64, blockIdx.y * 64, As, Bs);
}

// ---- gate (+zero QP/RESULT) -> [bar] -> q into QP | res_h into RESULT : grid 128, block 256 ----
__global__ void __launch_bounds__(256) k_gateq(
        const float* __restrict__ lh, const float* __restrict__ bih,
        const float* __restrict__ bhh, const float* __restrict__ b1,
        const float* __restrict__ w1, const float* __restrict__ w3,
        const float* __restrict__ b3) {
    __shared__ float As[32][65];
    __shared__ float Bs[32][65];
    __shared__ float red[8];
    const int t = threadIdx.x, bid = blockIdx.x;
    const int lane = t & 31, w = t >> 5;

    if (bid < 64) {
        const int b = bid;
        float qb1p = 0.f;
#pragma unroll
        for (int half = 0; half < 2; half++) {
            int j = t + half * 256;
            float gir = bih[j],        ghr = bhh[j];
            float giz = bih[512 + j],  ghz = bhh[512 + j];
            float gin = bih[1024 + j], ghn = bhh[1024 + j];
#pragma unroll
            for (int p = 0; p < KS; p++) {
                const float* gi = g_scr + OFF_GIP + p * (64 * 1536) + b * 1536;
                const float* gh = g_scr + OFF_GHP + p * (64 * 1536) + b * 1536;
                gir += gi[j];        ghr += gh[j];
                giz += gi[512 + j];  ghz += gh[512 + j];
                gin += gi[1024 + j]; ghn += gh[1024 + j];
            }
            float r = 1.f / (1.f + expf(-(gir + ghr)));
            float z = 1.f / (1.f + expf(-(giz + ghz)));
            float n = tanhf(gin + r * ghn);
            float hn = (1.f - z) * n + z * lh[b * Hc + j];
            g_scr[OFF_HNEW + b * Hc + j] = hn;
            g_scr[OFF_RESULT + b * Hc + j] = 0.f;
            g_scr[OFF_QP + b * Hc + j] = 0.f;
            qb1p += hn * b1[j];
        }
        float p = qb1p;
#pragma unroll
        for (int o = 16; o; o >>= 1) p += __shfl_xor_sync(0xffffffffu, p, o);
        if (lane == 0) red[w] = p;
        __syncthreads();
        if (t < 8) {
            float v = red[t];
#pragma unroll
            for (int o = 4; o; o >>= 1) v += __shfl_xor_sync(0x000000ffu, v, o);
            if (t == 0) g_scr[OFF_QB1 + b] = v;
        }
    }
    gridbar(0, 128);

    if (bid < 64) {
        gemm_ab_tile<2, true, true>(g_scr + OFF_HNEW, Hc, w1, Hc,
                                    g_scr + OFF_QP, Hc,
                                    (bid >> 3) * 64, (bid & 7) * 64, As, Bs);
    } else {
        int b2i = bid - 64;
        gemm_bt_tile<2, true, true>(g_scr + OFF_HNEW, Hc, w3 + 512, 1024,
                                    g_scr + OFF_RESULT, Hc, b3, (b2i & 7) == 0,
                                    (b2i >> 3) * 64, (b2i & 7) * 64, As, Bs);
    }
}

// ================= ATTN: streaming score + online softmax + context ===========
// grid 1024 (16 slices/beam), block 256, 64 rows/block in 16 chunks of 4 rows.
// Register-resident chunk: data read from smem exactly once per chunk.
__device__ __forceinline__ void cp_prefetch4(float4* dst, const float4* src, int t) {
#pragma unroll
    for (int i = 0; i < 2; i++) {
        unsigned d = (unsigned)__cvta_generic_to_shared(dst + t + i * 256);
        asm volatile("cp.async.cg.shared.global [%0], [%1], 16;\n" :: "r"(d), "l"(src + t + i * 256));
    }
    asm volatile("cp.async.commit_group;\n");
}

__global__ void __launch_bounds__(256, 7) k_attn(const float* __restrict__ enc,
                                                 const float* __restrict__ mask) {
    constexpr float inv_div = 0.04419417382415922f;  // 1/sqrt(512)
    __shared__ float4 buf[2][512];   // 2 x (4 rows x 512 f32) = 16KB
    __shared__ float partials[32];
    __shared__ float ws[4];
    __shared__ float smask[64];

    const int t = threadIdx.x;
    const int b = blockIdx.x >> 4;
    const int slice = blockIdx.x & 15;
    const int sbase = slice * 64;
    const float* encb = enc + (size_t)b * Sc * Hc;

    const float q0 = g_scr[OFF_QP + b * Hc + t] * inv_div;
    const float q1 = g_scr[OFF_QP + b * Hc + t + 256] * inv_div;
    if (t < 64) smask[t] = mask[b * Sc + sbase + t];
    const float cb = g_scr[OFF_QB1 + b] * inv_div;

    const int w = t >> 5, lane = t & 31;
    float m = -INFINITY, l = 0.f, a0 = 0.f, a1 = 0.f;

    cp_prefetch4(buf[0], reinterpret_cast<const float4*>(encb + (size_t)sbase * Hc), t);

    for (int c = 0; c < 16; c++) {
        asm volatile("cp.async.wait_group 0;\n");
        __syncthreads();   // chunk c ready; prev chunk's buf/partials/ws fully consumed

        if (c < 15)
            cp_prefetch4(buf[(c + 1) & 1],
                         reinterpret_cast<const float4*>(encb + (size_t)(sbase + (c + 1) * 4) * Hc), t);

        const float* ch = reinterpret_cast<const float*>(buf[c & 1]);

        // one smem read per value: 4 rows x (col t, col t+256)
        float v0 = ch[t],        u0 = ch[t + 256];
        float v1 = ch[512 + t],  u1 = ch[768 + t];
        float v2 = ch[1024 + t], u2 = ch[1280 + t];
        float v3 = ch[1536 + t], u3 = ch[1792 + t];

        float p0 = v0 * q0 + u0 * q1;
        float p1 = v1 * q0 + u1 * q1;
        float p2 = v2 * q0 + u2 * q1;
        float p3 = v3 * q0 + u3 * q1;
#pragma unroll
        for (int o = 16; o; o >>= 1) {
            p0 += __shfl_xor_sync(0xffffffffu, p0, o);
            p1 += __shfl_xor_sync(0xffffffffu, p1, o);
            p2 += __shfl_xor_sync(0xffffffffu, p2, o);
            p3 += __shfl_xor_sync(0xffffffffu, p3, o);
        }
        if (lane == 0) {
            partials[w * 4 + 0] = p0;
            partials[w * 4 + 1] = p1;
            partials[w * 4 + 2] = p2;
            partials[w * 4 + 3] = p3;
        }
        __syncthreads();

        // every thread: final row sums from 32 broadcast reads
        float sc0 = cb + smask[c * 4 + 0];
        float sc1 = cb + smask[c * 4 + 1];
        float sc2 = cb + smask[c * 4 + 2];
        float sc3 = cb + smask[c * 4 + 3];
#pragma unroll
        for (int p = 0; p < 8; p++) {
            sc0 += partials[p * 4 + 0];
            sc1 += partials[p * 4 + 1];
            sc2 += partials[p * 4 + 2];
            sc3 += partials[p * 4 + 3];
        }
        if (t == 0) {
            const int s0 = sbase + c * 4;
            g_scr[OFF_ATTN + b * Sc + s0 + 0] = sc0;
            g_scr[OFF_ATTN + b * Sc + s0 + 1] = sc1;
            g_scr[OFF_ATTN + b * Sc + s0 + 2] = sc2;
            g_scr[OFF_ATTN + b * Sc + s0 + 3] = sc3;
        }

        float cm = fmaxf(fmaxf(sc0, sc1), fmaxf(sc2, sc3));
        float nm = fmaxf(m, cm);
        if (nm > m) {
            float scale = expf(m - nm);
            a0 *= scale; a1 *= scale; l *= scale;
        }
        if (t < 4) {
            float scv = (t == 0) ? sc0 : (t == 1) ? sc1 : (t == 2) ? sc2 : sc3;
            ws[t] = expf(scv - nm);
        }
        __syncthreads();

        float w0 = ws[0], w1 = ws[1], w2 = ws[2], w3 = ws[3];
        l += w0 + w1 + w2 + w3;
        a0 += w0 * v0 + w1 * v1 + w2 * v2 + w3 * v3;
        a1 += w0 * u0 + w1 * u1 + w2 * u2 + w3 * u3;
        m = nm;
        // next iteration's first sync protects buf/partials/ws
    }
    const int pid = blockIdx.x;
    if (t == 0) { g_scr[OFF_PARTM + pid] = m; g_scr[OFF_PARTL + pid] = l; }
    g_scr[OFF_PARTACC + pid * 512 + t]       = a0;
    g_scr[OFF_PARTACC + pid * 512 + t + 256] = a1;
}

// ================= TAIL: combine+topk -> ctx -> res -> select+gather : grid 64, block 256 ======
__global__ void __launch_bounds__(256) k_tail(
        const float* __restrict__ evid, const int* __restrict__ esi,
        const float* __restrict__ prev_scores, const float* __restrict__ mask,
        const float* __restrict__ w2, const float* __restrict__ b2,
        const float* __restrict__ w3, float* __restrict__ out) {
    __shared__ float As[32][65];
    __shared__ float Bs[32][65];
    __shared__ float sv[1024];
    __shared__ int pick[4];
    __shared__ float pickv[4];
    __shared__ float wvv[8];
    __shared__ int wii[8];
    __shared__ int ssels[64];
    __shared__ int ssent[64];
    const int b = blockIdx.x, t = threadIdx.x;
    const int lane = t & 31, w = t >> 5;

    // ---- P0: combine partials -> ctxraw, zero CTX, top-4, TKLOG ----
    {
        float pm[SLICES], e[SLICES];
        float M = -INFINITY;
#pragma unroll
        for (int p = 0; p < SLICES; p++) { pm[p] = g_scr[OFF_PARTM + b * SLICES + p]; M = fmaxf(M, pm[p]); }
        float L = 0.f;
#pragma unroll
        for (int p = 0; p < SLICES; p++) { e[p] = expf(pm[p] - M); L += g_scr[OFF_PARTL + b * SLICES + p] * e[p]; }
        float invL = 1.f / L;
#pragma unroll
        for (int half = 0; half < 2; half++) {
            int col = t + half * 256;
            float s = 0.f;
#pragma unroll
            for (int p = 0; p < SLICES; p++)
                s += e[p] * g_scr[OFF_PARTACC + (b * SLICES + p) * 512 + col];
            g_scr[OFF_CTXRAW + b * Hc + col] = s * invL;
            g_scr[OFF_CTX + b * Hc + col] = 0.f;
        }
#pragma unroll
        for (int i = 0; i < 4; i++) sv[t + i * 256] = g_scr[OFF_ATTN + b * Sc + t + i * 256];
        __syncthreads();
        for (int round = 0; round < 4; round++) {
            float best = -INFINITY;
            int bi = 0x7fffffff;
#pragma unroll
            for (int u = 0; u < 4; u++) {
                int idx = t * 4 + u;
                bool skip = false;
                for (int rr = 0; rr < round; rr++) skip |= (pick[rr] == idx);
                float v = sv[idx];
                if (!skip && (v > best || (v == best && idx < bi))) { best = v; bi = idx; }
            }
#pragma unroll
            for (int o = 16; o; o >>= 1) {
                float ov = __shfl_xor_sync(0xffffffffu, best, o);
                int   oi = __shfl_xor_sync(0xffffffffu, bi, o);
                if (ov > best || (ov == best && oi < bi)) { best = ov; bi = oi; }
            }
            if (lane == 0) { wvv[w] = best; wii[w] = bi; }
            __syncthreads();
            if (t == 0) {
                float bb = wvv[0]; int bj = wii[0];
                for (int k = 1; k < 8; k++)
                    if (wvv[k] > bb || (wvv[k] == bb && wii[k] < bj)) { bb = wvv[k]; bj = wii[k]; }
                pick[round] = bj; pickv[round] = bb;
            }
            __syncthreads();
        }
        if (t < 4) {
            g_scr[OFF_TKLOG + b * 4 + t] = (M - pickv[t]) + logf(L) + evid[b];
            g_tkidx[b * 4 + t] = pick[t];
        }
    }
    gridbar(1, 64);

    // ---- P1: ctx GEMM: CTX += ctxraw @ w2^T + b2  (8 jt x 8 kt) ----
    gemm_bt_tile<2, true, true>(g_scr + OFF_CTXRAW, Hc, w2, Hc,
                                g_scr + OFF_CTX, Hc, b2, (b & 7) == 0,
                                (b >> 3) * 64, (b & 7) * 64, As, Bs);
    gridbar(2, 64);

    // ---- P2: res GEMM: RESULT += CTX @ w3[:, :512]^T ----
    gemm_bt_tile<2, true, true>(g_scr + OFF_CTX, Hc, w3, 1024,
                                g_scr + OFF_RESULT, Hc, nullptr, false,
                                (b >> 3) * 64, (b & 7) * 64, As, Bs);
    gridbar(3, 64);

    // ---- P3: beam selection (every block, for its own gather) + gather ----
    {
#pragma unroll
        for (int it2 = 0; it2 < 2; it2++) {
            int wb = w * 2 + it2;
            float v = (lane < 16) ? __ldcg(&g_scr[OFF_TKLOG + wb * 16 + lane]) : INFINITY;
            int rank = 0;
#pragma unroll
            for (int j = 0; j < 16; j++) {
                float vj = __shfl_sync(0xffffffffu, v, j);
                rank += (vj < v) || (vj == v && j < lane);
            }
            if (lane < 16 && rank < 4) {
                int k = wb * 4 + rank;
                int s = wb * 4 + (lane >> 2);
                int rr = lane & 3;
                int sent = __ldcg(&g_tkidx[s * 4 + rr]);
                ssels[k] = s;
                ssent[k] = sent;
                if (b == 0) {
                    out[O_SCORES + k] = v;
                    out[O_IDX + k * 4 + 0] = (float)esi[s * 3 + 0];
                    out[O_IDX + k * 4 + 1] = (float)esi[s * 3 + 1];
                    out[O_IDX + k * 4 + 2] = (float)esi[s * 3 + 2];
                    out[O_IDX + k * 4 + 3] = (float)sent;
                }
            }
        }
    }
    __syncthreads();

    for (int i = b * 256 + t; i < 393216; i += 64 * 256) {
        if (i < 32768) {
            int bi = i >> 9, j = i & 511;
            out[O_RESULT + i] = __ldcg(&g_scr[OFF_RESULT + ssels[bi] * 512 + j]);
        } else if (i < 65536) {
            int j = i - 32768;
            out[O_HIDDEN + j] = g_scr[OFF_HNEW + ssels[j >> 9] * 512 + (j & 511)];
        } else if (i < 327680) {
            int j = i - 65536;
            int p = j >> 16;
            int rem = j & 65535;
            int bi = rem >> 10, scol = rem & 1023;
            int s = ssels[bi];
            float v = (p < 3) ? prev_scores[p * 65536 + s * 1024 + scol]
                              : g_scr[OFF_ATTN + s * 1024 + scol];
            out[O_ATTNS + j] = v;
        } else {
            int j = i - 327680;
            int bi = j >> 10, scol = j & 1023;
            int s = ssels[bi];
            float v = (scol == ssent[bi]) ? NEG_INF_VAL : mask[s * 1024 + scol];
            out[O_MASK + j] = v;
        }
    }
}

// ---------------- launch ----------------
extern "C" void kernel_launch(void* const* d_in, const int* in_sizes, int n_in,
                              void* d_out, int out_size) {
    const float* last_hidden = (const float*)d_in[0];
    const float* dec_inputs  = (const float*)d_in[1];
    const float* enc         = (const float*)d_in[2];
    const float* prev_scores = (const float*)d_in[3];
    const float* mask        = (const float*)d_in[4];
    const float* evid        = (const float*)d_in[5];
    const int*   esi         = (const int*)d_in[6];
    const float* w1  = (const float*)d_in[7];
    const float* b1  = (const float*)d_in[8];
    const float* w2  = (const float*)d_in[9];
    const float* b2  = (const float*)d_in[10];
    const float* w3  = (const float*)d_in[11];
    const float* b3  = (const float*)d_in[12];
    const float* wih = (const float*)d_in[13];
    const float* whh = (const float*)d_in[14];
    const float* bih = (const float*)d_in[15];
    const float* bhh = (const float*)d_in[16];
    float* out = (float*)d_out;

    k_gru<<<dim3(24, KS, 2), 256>>>(dec_inputs, last_hidden, wih, whh);
    k_gateq<<<128, 256>>>(last_hidden, bih, bhh, b1, w1, w3, b3);
    k_attn<<<1024, 256>>>(enc, mask);
    k_tail<<<64, 256>>>(evid, esi, prev_scores, mask, w2, b2, w3, out);
}

// round 10
// speedup vs baseline: 1.0642x; 1.0642x over previous
#include <cuda_runtime.h>
#include <math.h>

#define NEG_INF_VAL -10000000000.0f

namespace {
constexpr int Hc = 512;
constexpr int Sc = 1024;
constexpr int KS = 8;          // split-K for H=512 GEMMs
constexpr int SLICES = 16;     // attn slices per beam
constexpr int NPART = 64 * SLICES;  // 1024

// float scratch offsets
constexpr int OFF_GIP     = 0;                          // KS*64*1536
constexpr int OFF_GHP     = OFF_GIP + KS * 64 * 1536;
constexpr int OFF_QP      = OFF_GHP + KS * 64 * 1536;   // 64*512 (atomic-accumulated)
constexpr int OFF_HNEW    = OFF_QP + 64 * 512;
constexpr int OFF_QB1     = OFF_HNEW + 64 * 512;
constexpr int OFF_ATTN    = OFF_QB1 + 64;               // 64x1024
constexpr int OFF_PARTM   = OFF_ATTN + 64 * 1024;
constexpr int OFF_PARTL   = OFF_PARTM + NPART;
constexpr int OFF_PARTACC = OFF_PARTL + NPART;          // 1024*512
constexpr int OFF_CTXRAW  = OFF_PARTACC + NPART * 512;
constexpr int OFF_CTX     = OFF_CTXRAW + 64 * 512;
constexpr int OFF_RESULT  = OFF_CTX + 64 * 512;
constexpr int OFF_TKLOG   = OFF_RESULT + 64 * 512;
constexpr int SCR_TOTAL   = OFF_TKLOG + 256;

// output layout (floats), tuple members concatenated in order
constexpr int O_RESULT = 0;
constexpr int O_HIDDEN = 32768;
constexpr int O_IDX    = 65536;
constexpr int O_ATTNS  = 65792;
constexpr int O_MASK   = 327936;
constexpr int O_SCORES = 393472;
}

__device__ __align__(16) float g_scr[SCR_TOTAL];
__device__ int g_tkidx[256];

// ---------------- GEMM tiles (64 rows x 64 cols, K-chunk = ITERS*32) ----------------
template<int ITERS, bool ATOMIC>
__device__ __forceinline__ void gemm_bt_tile(const float* __restrict__ A, int lda,
                                             const float* __restrict__ B, int ldb,
                                             float* __restrict__ C, int ldc,
                                             const float* __restrict__ bias, bool addBias,
                                             int j0, int k0,
                                             float (*As)[65], float (*Bs)[65]) {
    const int t = threadIdx.x;
    const int bx = (t & 15) * 4;
    const int by = (t >> 4) * 4;
    float acc[4][4] = {};
#pragma unroll
    for (int it = 0; it < ITERS; it++) {
        const int kk = k0 + it * 32;
#pragma unroll
        for (int i = 0; i < 8; i++) {
            int idx = t + i * 256;
            int r = idx >> 5, c = idx & 31;
            As[c][r] = A[r * lda + kk + c];
            Bs[c][r] = B[(j0 + r) * ldb + kk + c];
        }
        __syncthreads();
#pragma unroll
        for (int c = 0; c < 32; c++) {
            float b0 = Bs[c][bx + 0], b1 = Bs[c][bx + 1], b2 = Bs[c][bx + 2], b3 = Bs[c][bx + 3];
#pragma unroll
            for (int r = 0; r < 4; r++) {
                float av = As[c][by + r];
                acc[r][0] += av * b0; acc[r][1] += av * b1;
                acc[r][2] += av * b2; acc[r][3] += av * b3;
            }
        }
        __syncthreads();
    }
#pragma unroll
    for (int r = 0; r < 4; r++)
#pragma unroll
        for (int cc = 0; cc < 4; cc++) {
            float v = acc[r][cc];
            if (addBias) v += bias[j0 + bx + cc];
            if (ATOMIC) atomicAdd(&C[(by + r) * ldc + j0 + bx + cc], v);
            else        C[(by + r) * ldc + j0 + bx + cc] = v;
        }
}

template<int ITERS, bool ATOMIC>
__device__ __forceinline__ void gemm_ab_tile(const float* __restrict__ A, int lda,
                                             const float* __restrict__ B, int ldb,
                                             float* __restrict__ C, int ldc,
                                             int j0, int k0,
                                             float (*As)[65], float (*Bs)[65]) {
    const int t = threadIdx.x;
    const int bx = (t & 15) * 4;
    const int by = (t >> 4) * 4;
    float acc[4][4] = {};
#pragma unroll
    for (int it = 0; it < ITERS; it++) {
        const int kk = k0 + it * 32;
#pragma unroll
        for (int i = 0; i < 8; i++) {
            int idx = t + i * 256;
            int r = idx >> 5, c = idx & 31;
            As[c][r] = A[r * lda + kk + c];
        }
#pragma unroll
        for (int i = 0; i < 8; i++) {
            int idx = t + i * 256;
            int c = idx >> 6, jj = idx & 63;
            Bs[c][jj] = B[(kk + c) * ldb + j0 + jj];
        }
        __syncthreads();
#pragma unroll
        for (int c = 0; c < 32; c++) {
            float b0 = Bs[c][bx + 0], b1 = Bs[c][bx + 1], b2 = Bs[c][bx + 2], b3 = Bs[c][bx + 3];
#pragma unroll
            for (int r = 0; r < 4; r++) {
                float av = As[c][by + r];
                acc[r][0] += av * b0; acc[r][1] += av * b1;
                acc[r][2] += av * b2; acc[r][3] += av * b3;
            }
        }
        __syncthreads();
    }
#pragma unroll
    for (int r = 0; r < 4; r++)
#pragma unroll
        for (int cc = 0; cc < 4; cc++) {
            if (ATOMIC) atomicAdd(&C[(by + r) * ldc + j0 + bx + cc], acc[r][cc]);
            else        C[(by + r) * ldc + j0 + bx + cc] = acc[r][cc];
        }
}

// ---- gi/gh partials: grid (24, KS, 2), block 256 ----
__global__ void __launch_bounds__(256) k_gru(const float* __restrict__ x, const float* __restrict__ h,
                                             const float* __restrict__ wih, const float* __restrict__ whh) {
    __shared__ float As[32][65];
    __shared__ float Bs[32][65];
    const float* A = blockIdx.z ? h : x;
    const float* B = blockIdx.z ? whh : wih;
    float* C = g_scr + (blockIdx.z ? OFF_GHP : OFF_GIP) + blockIdx.y * (64 * 1536);
    gemm_bt_tile<2, false>(A, Hc, B, Hc, C, 1536, nullptr, false,
                           blockIdx.x * 64, blockIdx.y * 64, As, Bs);
}

// ---- GRU gates + qb1 + zero RESULT/QP: grid 64, block 512 ----
__global__ void __launch_bounds__(512) k_gate(const float* __restrict__ lh, const float* __restrict__ bih,
                                              const float* __restrict__ bhh, const float* __restrict__ b1) {
    int b = blockIdx.x, j = threadIdx.x;
    float gir = bih[j],        ghr = bhh[j];
    float giz = bih[512 + j],  ghz = bhh[512 + j];
    float gin = bih[1024 + j], ghn = bhh[1024 + j];
#pragma unroll
    for (int p = 0; p < KS; p++) {
        const float* gi = g_scr + OFF_GIP + p * (64 * 1536) + b * 1536;
        const float* gh = g_scr + OFF_GHP + p * (64 * 1536) + b * 1536;
        gir += gi[j];        ghr += gh[j];
        giz += gi[512 + j];  ghz += gh[512 + j];
        gin += gi[1024 + j]; ghn += gh[1024 + j];
    }
    float r = 1.f / (1.f + expf(-(gir + ghr)));
    float z = 1.f / (1.f + expf(-(giz + ghz)));
    float n = tanhf(gin + r * ghn);
    float hv = lh[b * Hc + j];
    float hn = (1.f - z) * n + z * hv;
    g_scr[OFF_HNEW + b * Hc + j] = hn;
    g_scr[OFF_RESULT + b * Hc + j] = 0.f;   // zero accumulator for result adds
    g_scr[OFF_QP + b * Hc + j] = 0.f;       // zero accumulator for q atomics

    float p = hn * b1[j];
    __shared__ float red[16];
#pragma unroll
    for (int o = 16; o; o >>= 1) p += __shfl_xor_sync(0xffffffffu, p, o);
    if ((j & 31) == 0) red[j >> 5] = p;
    __syncthreads();
    if (j < 16) {
        float v = red[j];
#pragma unroll
        for (int o = 8; o; o >>= 1) v += __shfl_xor_sync(0x0000ffffu, v, o);
        if (j == 0) g_scr[OFF_QB1 + b] = v;
    }
}

// ---- q (z=0, atomic into QP) + RESULT += hnew @ w3[:,512:]^T + b3 (z=1): grid (8, KS, 2) ----
__global__ void __launch_bounds__(256) k_q2(const float* __restrict__ w1,
                                            const float* __restrict__ w3,
                                            const float* __restrict__ b3) {
    __shared__ float As[32][65];
    __shared__ float Bs[32][65];
    if (blockIdx.z == 0) {
        gemm_ab_tile<2, true>(g_scr + OFF_HNEW, Hc, w1, Hc,
                              g_scr + OFF_QP, Hc,
                              blockIdx.x * 64, blockIdx.y * 64, As, Bs);
    } else {
        gemm_bt_tile<2, true>(g_scr + OFF_HNEW, Hc, w3 + 512, 1024,
                              g_scr + OFF_RESULT, Hc, b3, blockIdx.y == 0,
                              blockIdx.x * 64, blockIdx.y * 64, As, Bs);
    }
}

// ================= ATTN: streaming score + online softmax + context ===========
// grid 1024 (16 slices/beam), block 256, 64 rows/block in 16 chunks of 4 rows.
// Register-resident chunk (one smem read per value), 3-stage cp.async pipeline.
__device__ __forceinline__ void cp_prefetch4(float4* dst, const float4* src, int t) {
#pragma unroll
    for (int i = 0; i < 2; i++) {
        unsigned d = (unsigned)__cvta_generic_to_shared(dst + t + i * 256);
        asm volatile("cp.async.cg.shared.global [%0], [%1], 16;\n" :: "r"(d), "l"(src + t + i * 256));
    }
    asm volatile("cp.async.commit_group;\n");
}

__global__ void __launch_bounds__(256, 7) k_attn(const float* __restrict__ enc,
                                                 const float* __restrict__ mask) {
    constexpr float inv_div = 0.04419417382415922f;  // 1/sqrt(512)
    __shared__ float4 buf[3][512];   // 3 x (4 rows x 512 f32) = 24KB
    __shared__ float partials[32];
    __shared__ float ws[4];
    __shared__ float smask[64];

    const int t = threadIdx.x;
    const int b = blockIdx.x >> 4;
    const int slice = blockIdx.x & 15;
    const int sbase = slice * 64;
    const float* encb = enc + (size_t)b * Sc * Hc;

    const float q0 = g_scr[OFF_QP + b * Hc + t] * inv_div;
    const float q1 = g_scr[OFF_QP + b * Hc + t + 256] * inv_div;
    if (t < 64) smask[t] = mask[b * Sc + sbase + t];
    const float cb = g_scr[OFF_QB1 + b] * inv_div;

    const int w = t >> 5, lane = t & 31;
    float m = -INFINITY, l = 0.f, a0 = 0.f, a1 = 0.f;

    cp_prefetch4(buf[0], reinterpret_cast<const float4*>(encb + (size_t)(sbase + 0) * Hc), t);
    cp_prefetch4(buf[1], reinterpret_cast<const float4*>(encb + (size_t)(sbase + 4) * Hc), t);

    for (int c = 0; c < 16; c++) {
        if (c < 15) asm volatile("cp.async.wait_group 1;\n");   // chunk c complete, c+1 may fly
        else        asm volatile("cp.async.wait_group 0;\n");
        __syncthreads();   // also: all threads finished consuming buf[(c+2)%3] (chunk c-1)

        if (c + 2 < 16)
            cp_prefetch4(buf[(c + 2) % 3],
                         reinterpret_cast<const float4*>(encb + (size_t)(sbase + (c + 2) * 4) * Hc), t);

        const float* ch = reinterpret_cast<const float*>(buf[c % 3]);

        // one smem read per value: 4 rows x (col t, col t+256)
        float v0 = ch[t],        u0 = ch[t + 256];
        float v1 = ch[512 + t],  u1 = ch[768 + t];
        float v2 = ch[1024 + t], u2 = ch[1280 + t];
        float v3 = ch[1536 + t], u3 = ch[1792 + t];

        float p0 = v0 * q0 + u0 * q1;
        float p1 = v1 * q0 + u1 * q1;
        float p2 = v2 * q0 + u2 * q1;
        float p3 = v3 * q0 + u3 * q1;
#pragma unroll
        for (int o = 16; o; o >>= 1) {
            p0 += __shfl_xor_sync(0xffffffffu, p0, o);
            p1 += __shfl_xor_sync(0xffffffffu, p1, o);
            p2 += __shfl_xor_sync(0xffffffffu, p2, o);
            p3 += __shfl_xor_sync(0xffffffffu, p3, o);
        }
        if (lane == 0) {
            partials[w * 4 + 0] = p0;
            partials[w * 4 + 1] = p1;
            partials[w * 4 + 2] = p2;
            partials[w * 4 + 3] = p3;
        }
        __syncthreads();

        // every thread: final row sums from 32 broadcast reads
        float sc0 = cb + smask[c * 4 + 0];
        float sc1 = cb + smask[c * 4 + 1];
        float sc2 = cb + smask[c * 4 + 2];
        float sc3 = cb + smask[c * 4 + 3];
#pragma unroll
        for (int p = 0; p < 8; p++) {
            sc0 += partials[p * 4 + 0];
            sc1 += partials[p * 4 + 1];
            sc2 += partials[p * 4 + 2];
            sc3 += partials[p * 4 + 3];
        }
        if (t == 0) {
            const int s0 = sbase + c * 4;
            g_scr[OFF_ATTN + b * Sc + s0 + 0] = sc0;
            g_scr[OFF_ATTN + b * Sc + s0 + 1] = sc1;
            g_scr[OFF_ATTN + b * Sc + s0 + 2] = sc2;
            g_scr[OFF_ATTN + b * Sc + s0 + 3] = sc3;
        }

        float cm = fmaxf(fmaxf(sc0, sc1), fmaxf(sc2, sc3));
        float nm = fmaxf(m, cm);
        if (nm > m) {
            float scale = expf(m - nm);
            a0 *= scale; a1 *= scale; l *= scale;
        }
        if (t < 4) {
            float scv = (t == 0) ? sc0 : (t == 1) ? sc1 : (t == 2) ? sc2 : sc3;
            ws[t] = expf(scv - nm);
        }
        __syncthreads();

        float w0 = ws[0], w1 = ws[1], w2 = ws[2], w3 = ws[3];
        l += w0 + w1 + w2 + w3;
        a0 += w0 * v0 + w1 * v1 + w2 * v2 + w3 * v3;
        a1 += w0 * u0 + w1 * u1 + w2 * u2 + w3 * u3;
        m = nm;
        // next iteration's first sync protects buf/partials/ws
    }
    const int pid = blockIdx.x;
    if (t == 0) { g_scr[OFF_PARTM + pid] = m; g_scr[OFF_PARTL + pid] = l; }
    g_scr[OFF_PARTACC + pid * 512 + t]       = a0;
    g_scr[OFF_PARTACC + pid * 512 + t + 256] = a1;
}

// ---- combine partials -> ctxraw, zero CTX, top-4, TKLOG: grid 64, block 256 ----
__global__ void __launch_bounds__(256) k_combine(const float* __restrict__ evid) {
    __shared__ float sv[1024];
    __shared__ int pick[4];
    __shared__ float pickv[4];
    __shared__ float wvv[8];
    __shared__ int wii[8];
    const int b = blockIdx.x, t = threadIdx.x;

    float pm[SLICES], e[SLICES];
    float M = -INFINITY;
#pragma unroll
    for (int p = 0; p < SLICES; p++) { pm[p] = g_scr[OFF_PARTM + b * SLICES + p]; M = fmaxf(M, pm[p]); }
    float L = 0.f;
#pragma unroll
    for (int p = 0; p < SLICES; p++) { e[p] = expf(pm[p] - M); L += g_scr[OFF_PARTL + b * SLICES + p] * e[p]; }
    float invL = 1.f / L;
#pragma unroll
    for (int half = 0; half < 2; half++) {
        int col = t + half * 256;
        float s = 0.f;
#pragma unroll
        for (int p = 0; p < SLICES; p++)
            s += e[p] * g_scr[OFF_PARTACC + (b * SLICES + p) * 512 + col];
        g_scr[OFF_CTXRAW + b * Hc + col] = s * invL;
        g_scr[OFF_CTX + b * Hc + col] = 0.f;
    }
#pragma unroll
    for (int i = 0; i < 4; i++) sv[t + i * 256] = g_scr[OFF_ATTN + b * Sc + t + i * 256];
    __syncthreads();
    for (int round = 0; round < 4; round++) {
        float best = -INFINITY;
        int bi = 0x7fffffff;
#pragma unroll
        for (int u = 0; u < 4; u++) {
            int idx = t * 4 + u;
            bool skip = false;
            for (int rr = 0; rr < round; rr++) skip |= (pick[rr] == idx);
            float v = sv[idx];
            if (!skip && (v > best || (v == best && idx < bi))) { best = v; bi = idx; }
        }
#pragma unroll
        for (int o = 16; o; o >>= 1) {
            float ov = __shfl_xor_sync(0xffffffffu, best, o);
            int   oi = __shfl_xor_sync(0xffffffffu, bi, o);
            if (ov > best || (ov == best && oi < bi)) { best = ov; bi = oi; }
        }
        if ((t & 31) == 0) { wvv[t >> 5] = best; wii[t >> 5] = bi; }
        __syncthreads();
        if (t == 0) {
            float bb = wvv[0]; int bj = wii[0];
            for (int k = 1; k < 8; k++)
                if (wvv[k] > bb || (wvv[k] == bb && wii[k] < bj)) { bb = wvv[k]; bj = wii[k]; }
            pick[round] = bj; pickv[round] = bb;
        }
        __syncthreads();
    }
    if (t < 4) {
        g_scr[OFF_TKLOG + b * 4 + t] = (M - pickv[t]) + logf(L) + evid[b];
        g_tkidx[b * 4 + t] = pick[t];
    }
}

// ---- ctx GEMM: CTX += ctxraw @ w2^T + b2 : grid (8, KS) ----
__global__ void __launch_bounds__(256) k_ctx(const float* __restrict__ w2, const float* __restrict__ b2) {
    __shared__ float As[32][65];
    __shared__ float Bs[32][65];
    gemm_bt_tile<2, true>(g_scr + OFF_CTXRAW, Hc, w2, Hc,
                          g_scr + OFF_CTX, Hc, b2, blockIdx.y == 0,
                          blockIdx.x * 64, blockIdx.y * 64, As, Bs);
}

// ---- res GEMM: RESULT += CTX @ w3[:, :512]^T : grid (8, KS) ----
__global__ void __launch_bounds__(256) k_res(const float* __restrict__ w3) {
    __shared__ float As[32][65];
    __shared__ float Bs[32][65];
    gemm_bt_tile<2, true>(g_scr + OFF_CTX, Hc, w3, 1024,
                          g_scr + OFF_RESULT, Hc, nullptr, false,
                          blockIdx.x * 64, blockIdx.y * 64, As, Bs);
}

// ---- gather (with fused beam selection): grid 768, block 512 ----
__global__ void __launch_bounds__(512) k_gather(const int* __restrict__ esi,
                                                const float* __restrict__ prev_scores,
                                                const float* __restrict__ mask,
                                                float* __restrict__ out) {
    __shared__ int ssels[64];
    __shared__ int ssent[64];
    const int t = threadIdx.x;
    const int wb = t >> 5, lane = t & 31;   // 16 warps = 16 batches

    {
        float v = (lane < 16) ? g_scr[OFF_TKLOG + wb * 16 + lane] : INFINITY;
        int rank = 0;
#pragma unroll
        for (int j = 0; j < 16; j++) {
            float vj = __shfl_sync(0xffffffffu, v, j);
            rank += (vj < v) || (vj == v && j < lane);
        }
        if (lane < 16 && rank < 4) {
            int k = wb * 4 + rank;
            int s = wb * 4 + (lane >> 2);
            int rr = lane & 3;
            int sent = g_tkidx[s * 4 + rr];
            ssels[k] = s;
            ssent[k] = sent;
            if (blockIdx.x == 0) {
                out[O_SCORES + k] = v;
                out[O_IDX + k * 4 + 0] = (float)esi[s * 3 + 0];
                out[O_IDX + k * 4 + 1] = (float)esi[s * 3 + 1];
                out[O_IDX + k * 4 + 2] = (float)esi[s * 3 + 2];
                out[O_IDX + k * 4 + 3] = (float)sent;
            }
        }
    }
    __syncthreads();

    int i = blockIdx.x * 512 + t;   // 768*512 = 393216 exact
    if (i < 32768) {
        int bi = i >> 9, j = i & 511;
        out[O_RESULT + i] = g_scr[OFF_RESULT + ssels[bi] * 512 + j];
    } else if (i < 65536) {
        int j = i - 32768;
        out[O_HIDDEN + j] = g_scr[OFF_HNEW + ssels[j >> 9] * 512 + (j & 511)];
    } else if (i < 327680) {
        int j = i - 65536;
        int p = j >> 16;
        int rem = j & 65535;
        int bi = rem >> 10, scol = rem & 1023;
        int s = ssels[bi];
        float v = (p < 3) ? prev_scores[p * 65536 + s * 1024 + scol]
                          : g_scr[OFF_ATTN + s * 1024 + scol];
        out[O_ATTNS + j] = v;
    } else {
        int j = i - 327680;
        int bi = j >> 10, scol = j & 1023;
        int s = ssels[bi];
        float v = (scol == ssent[bi]) ? NEG_INF_VAL : mask[s * 1024 + scol];
        out[O_MASK + j] = v;
    }
}

// ---------------- launch ----------------
extern "C" void kernel_launch(void* const* d_in, const int* in_sizes, int n_in,
                              void* d_out, int out_size) {
    const float* last_hidden = (const float*)d_in[0];
    const float* dec_inputs  = (const float*)d_in[1];
    const float* enc         = (const float*)d_in[2];
    const float* prev_scores = (const float*)d_in[3];
    const float* mask        = (const float*)d_in[4];
    const float* evid        = (const float*)d_in[5];
    const int*   esi         = (const int*)d_in[6];
    const float* w1  = (const float*)d_in[7];
    const float* b1  = (const float*)d_in[8];
    const float* w2  = (const float*)d_in[9];
    const float* b2  = (const float*)d_in[10];
    const float* w3  = (const float*)d_in[11];
    const float* b3  = (const float*)d_in[12];
    const float* wih = (const float*)d_in[13];
    const float* whh = (const float*)d_in[14];
    const float* bih = (const float*)d_in[15];
    const float* bhh = (const float*)d_in[16];
    float* out = (float*)d_out;

    k_gru<<<dim3(24, KS, 2), 256>>>(dec_inputs, last_hidden, wih, whh);
    k_gate<<<64, 512>>>(last_hidden, bih, bhh, b1);
    k_q2<<<dim3(8, KS, 2), 256>>>(w1, w3, b3);
    k_attn<<<1024, 256>>>(enc, mask);
    k_combine<<<64, 256>>>(evid);
    k_ctx<<<dim3(8, KS), 256>>>(w2, b2);
    k_res<<<dim3(8, KS), 256>>>(w3);
    k_gather<<<768, 512>>>(esi, prev_scores, mask, out);
}

// round 12
// speedup vs baseline: 1.1403x; 1.0714x over previous
#include <cuda_runtime.h>
#include <math.h>

#define NEG_INF_VAL -10000000000.0f

namespace {
constexpr int Hc = 512;
constexpr int Sc = 1024;
constexpr int KS = 8;          // split-K for H=512 GEMMs
constexpr int SLICES = 16;     // attn slices per beam
constexpr int NPART = 64 * SLICES;  // 1024

// float scratch offsets
constexpr int OFF_GIP     = 0;                          // KS*64*1536
constexpr int OFF_GHP     = OFF_GIP + KS * 64 * 1536;
constexpr int OFF_QP      = OFF_GHP + KS * 64 * 1536;   // 64*512 (atomic-accumulated)
constexpr int OFF_HNEW    = OFF_QP + 64 * 512;
constexpr int OFF_QB1     = OFF_HNEW + 64 * 512;
constexpr int OFF_ATTN    = OFF_QB1 + 64;               // 64x1024
constexpr int OFF_PARTM   = OFF_ATTN + 64 * 1024;
constexpr int OFF_PARTL   = OFF_PARTM + NPART;
constexpr int OFF_PARTACC = OFF_PARTL + NPART;          // 1024*512
constexpr int OFF_CTXRAW  = OFF_PARTACC + NPART * 512;
constexpr int OFF_CTX     = OFF_CTXRAW + 64 * 512;
constexpr int OFF_RESULT  = OFF_CTX + 64 * 512;
constexpr int OFF_TKLOG   = OFF_RESULT + 64 * 512;
constexpr int SCR_TOTAL   = OFF_TKLOG + 256;

// output layout (floats), tuple members concatenated in order
constexpr int O_RESULT = 0;
constexpr int O_HIDDEN = 32768;
constexpr int O_IDX    = 65536;
constexpr int O_ATTNS  = 65792;
constexpr int O_MASK   = 327936;
constexpr int O_SCORES = 393472;
}

__device__ __align__(16) float g_scr[SCR_TOTAL];
__device__ int g_tkidx[256];
__device__ int g_cnt[64];      // per-beam slice-completion counters (zeroed by k_gate each launch)

// ---------------- GEMM tiles (64 rows x 64 cols, K-chunk = ITERS*32) ----------------
template<int ITERS, bool ATOMIC>
__device__ __forceinline__ void gemm_bt_tile(const float* __restrict__ A, int lda,
                                             const float* __restrict__ B, int ldb,
                                             float* __restrict__ C, int ldc,
                                             const float* __restrict__ bias, bool addBias,
                                             int j0, int k0,
                                             float (*As)[65], float (*Bs)[65]) {
    const int t = threadIdx.x;
    const int bx = (t & 15) * 4;
    const int by = (t >> 4) * 4;
    float acc[4][4] = {};
#pragma unroll
    for (int it = 0; it < ITERS; it++) {
        const int kk = k0 + it * 32;
#pragma unroll
        for (int i = 0; i < 8; i++) {
            int idx = t + i * 256;
            int r = idx >> 5, c = idx & 31;
            As[c][r] = A[r * lda + kk + c];
            Bs[c][r] = B[(j0 + r) * ldb + kk + c];
        }
        __syncthreads();
#pragma unroll
        for (int c = 0; c < 32; c++) {
            float b0 = Bs[c][bx + 0], b1 = Bs[c][bx + 1], b2 = Bs[c][bx + 2], b3 = Bs[c][bx + 3];
#pragma unroll
            for (int r = 0; r < 4; r++) {
                float av = As[c][by + r];
                acc[r][0] += av * b0; acc[r][1] += av * b1;
                acc[r][2] += av * b2; acc[r][3] += av * b3;
            }
        }
        __syncthreads();
    }
#pragma unroll
    for (int r = 0; r < 4; r++)
#pragma unroll
        for (int cc = 0; cc < 4; cc++) {
            float v = acc[r][cc];
            if (addBias) v += bias[j0 + bx + cc];
            if (ATOMIC) atomicAdd(&C[(by + r) * ldc + j0 + bx + cc], v);
            else        C[(by + r) * ldc + j0 + bx + cc] = v;
        }
}

template<int ITERS, bool ATOMIC>
__device__ __forceinline__ void gemm_ab_tile(const float* __restrict__ A, int lda,
                                             const float* __restrict__ B, int ldb,
                                             float* __restrict__ C, int ldc,
                                             int j0, int k0,
                                             float (*As)[65], float (*Bs)[65]) {
    const int t = threadIdx.x;
    const int bx = (t & 15) * 4;
    const int by = (t >> 4) * 4;
    float acc[4][4] = {};
#pragma unroll
    for (int it = 0; it < ITERS; it++) {
        const int kk = k0 + it * 32;
#pragma unroll
        for (int i = 0; i < 8; i++) {
            int idx = t + i * 256;
            int r = idx >> 5, c = idx & 31;
            As[c][r] = A[r * lda + kk + c];
        }
#pragma unroll
        for (int i = 0; i < 8; i++) {
            int idx = t + i * 256;
            int c = idx >> 6, jj = idx & 63;
            Bs[c][jj] = B[(kk + c) * ldb + j0 + jj];
        }
        __syncthreads();
#pragma unroll
        for (int c = 0; c < 32; c++) {
            float b0 = Bs[c][bx + 0], b1 = Bs[c][bx + 1], b2 = Bs[c][bx + 2], b3 = Bs[c][bx + 3];
#pragma unroll
            for (int r = 0; r < 4; r++) {
                float av = As[c][by + r];
                acc[r][0] += av * b0; acc[r][1] += av * b1;
                acc[r][2] += av * b2; acc[r][3] += av * b3;
            }
        }
        __syncthreads();
    }
#pragma unroll
    for (int r = 0; r < 4; r++)
#pragma unroll
        for (int cc = 0; cc < 4; cc++) {
            if (ATOMIC) atomicAdd(&C[(by + r) * ldc + j0 + bx + cc], acc[r][cc]);
            else        C[(by + r) * ldc + j0 + bx + cc] = acc[r][cc];
        }
}

// ---- gi/gh partials: grid (24, KS, 2), block 256 ----
__global__ void __launch_bounds__(256) k_gru(const float* __restrict__ x, const float* __restrict__ h,
                                             const float* __restrict__ wih, const float* __restrict__ whh) {
    __shared__ float As[32][65];
    __shared__ float Bs[32][65];
    const float* A = blockIdx.z ? h : x;
    const float* B = blockIdx.z ? whh : wih;
    float* C = g_scr + (blockIdx.z ? OFF_GHP : OFF_GIP) + blockIdx.y * (64 * 1536);
    gemm_bt_tile<2, false>(A, Hc, B, Hc, C, 1536, nullptr, false,
                           blockIdx.x * 64, blockIdx.y * 64, As, Bs);
}

// ---- GRU gates + qb1 + zero RESULT/QP + zero slice counters: grid 64, block 512 ----
__global__ void __launch_bounds__(512) k_gate(const float* __restrict__ lh, const float* __restrict__ bih,
                                              const float* __restrict__ bhh, const float* __restrict__ b1) {
    int b = blockIdx.x, j = threadIdx.x;
    if (j == 0) g_cnt[b] = 0;   // reset per-beam slice counter every launch (graph-replay safe)
    float gir = bih[j],        ghr = bhh[j];
    float giz = bih[512 + j],  ghz = bhh[512 + j];
    float gin = bih[1024 + j], ghn = bhh[1024 + j];
#pragma unroll
    for (int p = 0; p < KS; p++) {
        const float* gi = g_scr + OFF_GIP + p * (64 * 1536) + b * 1536;
        const float* gh = g_scr + OFF_GHP + p * (64 * 1536) + b * 1536;
        gir += gi[j];        ghr += gh[j];
        giz += gi[512 + j];  ghz += gh[512 + j];
        gin += gi[1024 + j]; ghn += gh[1024 + j];
    }
    float r = 1.f / (1.f + expf(-(gir + ghr)));
    float z = 1.f / (1.f + expf(-(giz + ghz)));
    float n = tanhf(gin + r * ghn);
    float hv = lh[b * Hc + j];
    float hn = (1.f - z) * n + z * hv;
    g_scr[OFF_HNEW + b * Hc + j] = hn;
    g_scr[OFF_RESULT + b * Hc + j] = 0.f;   // zero accumulator for result adds
    g_scr[OFF_QP + b * Hc + j] = 0.f;       // zero accumulator for q atomics

    float p = hn * b1[j];
    __shared__ float red[16];
#pragma unroll
    for (int o = 16; o; o >>= 1) p += __shfl_xor_sync(0xffffffffu, p, o);
    if ((j & 31) == 0) red[j >> 5] = p;
    __syncthreads();
    if (j < 16) {
        float v = red[j];
#pragma unroll
        for (int o = 8; o; o >>= 1) v += __shfl_xor_sync(0x0000ffffu, v, o);
        if (j == 0) g_scr[OFF_QB1 + b] = v;
    }
}

// ---- q (z=0, atomic into QP) + RESULT += hnew @ w3[:,512:]^T + b3 (z=1): grid (8, KS, 2) ----
__global__ void __launch_bounds__(256) k_q2(const float* __restrict__ w1,
                                            const float* __restrict__ w3,
                                            const float* __restrict__ b3) {
    __shared__ float As[32][65];
    __shared__ float Bs[32][65];
    if (blockIdx.z == 0) {
        gemm_ab_tile<2, true>(g_scr + OFF_HNEW, Hc, w1, Hc,
                              g_scr + OFF_QP, Hc,
                              blockIdx.x * 64, blockIdx.y * 64, As, Bs);
    } else {
        gemm_bt_tile<2, true>(g_scr + OFF_HNEW, Hc, w3 + 512, 1024,
                              g_scr + OFF_RESULT, Hc, b3, blockIdx.y == 0,
                              blockIdx.x * 64, blockIdx.y * 64, As, Bs);
    }
}

// ================= ATTN: streaming score + online softmax + context + fused combine =========
// grid 1024 (16 slices/beam), block 256, 64 rows/block in 8 chunks of 8 rows, double-buffered.
// float2 columns: thread t owns cols (2t, 2t+1). Last slice block per beam does the combine.
__device__ __forceinline__ void cp_prefetch(float4* dst, const float4* src, int t) {
#pragma unroll
    for (int i = 0; i < 4; i++) {
        unsigned d = (unsigned)__cvta_generic_to_shared(dst + t + i * 256);
        asm volatile("cp.async.cg.shared.global [%0], [%1], 16;\n" :: "r"(d), "l"(src + t + i * 256));
    }
    asm volatile("cp.async.commit_group;\n");
}

__global__ void __launch_bounds__(256, 6) k_attn(const float* __restrict__ enc,
                                                 const float* __restrict__ mask,
                                                 const float* __restrict__ evid) {
    constexpr float inv_div = 0.04419417382415922f;  // 1/sqrt(512)
    __shared__ float2 qs2[256];       // 2KB
    __shared__ float4 buf[2][1024];   // 2 x (8 rows x 512 f32) = 32KB
    __shared__ float scs[8];
    __shared__ float ws[8];
    __shared__ float smask[64];
    __shared__ float e_sh[16];
    __shared__ int   s_last;
    __shared__ int   pick[4];
    __shared__ float pickv[4];
    __shared__ float wvv[8];
    __shared__ int   wii[8];

    const int t = threadIdx.x;
    const int b = blockIdx.x >> 4;
    const int slice = blockIdx.x & 15;
    const int sbase = slice * 64;
    const float* encb = enc + (size_t)b * Sc * Hc;

    {
        float2 q = reinterpret_cast<const float2*>(g_scr + OFF_QP + b * Hc)[t];
        qs2[t] = make_float2(q.x * inv_div, q.y * inv_div);
    }
    if (t < 64) smask[t] = mask[b * Sc + sbase + t];
    const float cb = g_scr[OFF_QB1 + b] * inv_div;

    const int w = t >> 5, lane = t & 31;
    float m = -INFINITY, l = 0.f;
    float ax = 0.f, ay = 0.f;

    cp_prefetch(buf[0], reinterpret_cast<const float4*>(encb + (size_t)sbase * Hc), t);

    for (int c = 0; c < 8; c++) {
        asm volatile("cp.async.wait_group 0;\n");
        __syncthreads();   // chunk c ready AND all threads done with buf[(c+1)&1] from iter c-1

        if (c < 7)
            cp_prefetch(buf[(c + 1) & 1],
                        reinterpret_cast<const float4*>(encb + (size_t)(sbase + (c + 1) * 8) * Hc), t);

        const float2* ch2 = reinterpret_cast<const float2*>(buf[c & 1]);
        const int s0 = sbase + c * 8;

        // scores: warp w handles row w (8 LDS.64 + 8 LDS.64)
        {
            float d = 0.f;
#pragma unroll
            for (int kk = 0; kk < 8; kk++) {
                int k = lane + kk * 32;
                float2 cv = ch2[w * 256 + k];
                float2 qv = qs2[k];
                d += cv.x * qv.x + cv.y * qv.y;
            }
#pragma unroll
            for (int o = 16; o; o >>= 1) d += __shfl_xor_sync(0xffffffffu, d, o);
            if (lane == 0) {
                float sc = d + cb + smask[c * 8 + w];
                scs[w] = sc;
                g_scr[OFF_ATTN + b * Sc + s0 + w] = sc;
            }
        }
        __syncthreads();

        float cm = scs[0];
#pragma unroll
        for (int r = 1; r < 8; r++) cm = fmaxf(cm, scs[r]);
        float nm = fmaxf(m, cm);
        if (nm > m) {
            float scale = expf(m - nm);
            ax *= scale; ay *= scale; l *= scale;
        }
        if (t < 8) ws[t] = expf(scs[t] - nm);
        __syncthreads();

        float lsum = 0.f;
#pragma unroll
        for (int r = 0; r < 8; r++) {
            float wr = ws[r];
            lsum += wr;
            float2 cv = ch2[r * 256 + t];
            ax += wr * cv.x;
            ay += wr * cv.y;
        }
        l += lsum;
        m = nm;
        // next iteration's first sync protects buf/ws/scs
    }
    const int pid = blockIdx.x;
    if (t == 0) { g_scr[OFF_PARTM + pid] = m; g_scr[OFF_PARTL + pid] = l; }
    reinterpret_cast<float2*>(g_scr + OFF_PARTACC + pid * 512)[t] = make_float2(ax, ay);

    // ---- last-arriving slice block of this beam performs the combine ----
    __threadfence();
    if (t == 0) s_last = (atomicAdd(&g_cnt[b], 1) == SLICES - 1);
    __syncthreads();
    if (!s_last) return;

    float M = -INFINITY;
#pragma unroll
    for (int p = 0; p < SLICES; p++)
        M = fmaxf(M, __ldcg(&g_scr[OFF_PARTM + b * SLICES + p]));
    if (t < SLICES)
        e_sh[t] = expf(__ldcg(&g_scr[OFF_PARTM + b * SLICES + t]) - M);
    __syncthreads();

    float L = 0.f;
#pragma unroll
    for (int p = 0; p < SLICES; p++)
        L += __ldcg(&g_scr[OFF_PARTL + b * SLICES + p]) * e_sh[p];
    float invL = 1.f / L;

#pragma unroll
    for (int half = 0; half < 2; half++) {
        int col = t + half * 256;
        float s = 0.f;
#pragma unroll
        for (int p = 0; p < SLICES; p++)
            s += e_sh[p] * __ldcg(&g_scr[OFF_PARTACC + (b * SLICES + p) * 512 + col]);
        g_scr[OFF_CTXRAW + b * Hc + col] = s * invL;
        g_scr[OFF_CTX + b * Hc + col] = 0.f;   // zero atomic target for ctx GEMM
    }

    // top-4 over this beam's scores (reuse buf smem as sv[1024])
    float* sv = reinterpret_cast<float*>(buf);
#pragma unroll
    for (int i = 0; i < 4; i++)
        sv[t + i * 256] = __ldcg(&g_scr[OFF_ATTN + b * Sc + t + i * 256]);
    __syncthreads();
    for (int round = 0; round < 4; round++) {
        float best = -INFINITY;
        int bi = 0x7fffffff;
#pragma unroll
        for (int u = 0; u < 4; u++) {
            int idx = t * 4 + u;
            bool skip = false;
            for (int rr = 0; rr < round; rr++) skip |= (pick[rr] == idx);
            float v = sv[idx];
            if (!skip && (v > best || (v == best && idx < bi))) { best = v; bi = idx; }
        }
#pragma unroll
        for (int o = 16; o; o >>= 1) {
            float ov = __shfl_xor_sync(0xffffffffu, best, o);
            int   oi = __shfl_xor_sync(0xffffffffu, bi, o);
            if (ov > best || (ov == best && oi < bi)) { best = ov; bi = oi; }
        }
        if (lane == 0) { wvv[w] = best; wii[w] = bi; }
        __syncthreads();
        if (t == 0) {
            float bb = wvv[0]; int bj = wii[0];
            for (int k = 1; k < 8; k++)
                if (wvv[k] > bb || (wvv[k] == bb && wii[k] < bj)) { bb = wvv[k]; bj = wii[k]; }
            pick[round] = bj; pickv[round] = bb;
        }
        __syncthreads();
    }
    if (t < 4) {
        g_scr[OFF_TKLOG + b * 4 + t] = (M - pickv[t]) + logf(L) + evid[b];
        g_tkidx[b * 4 + t] = pick[t];
    }
}

// ---- ctx GEMM: CTX += ctxraw @ w2^T + b2 : grid (8, KS) ----
__global__ void __launch_bounds__(256) k_ctx(const float* __restrict__ w2, const float* __restrict__ b2) {
    __shared__ float As[32][65];
    __shared__ float Bs[32][65];
    gemm_bt_tile<2, true>(g_scr + OFF_CTXRAW, Hc, w2, Hc,
                          g_scr + OFF_CTX, Hc, b2, blockIdx.y == 0,
                          blockIdx.x * 64, blockIdx.y * 64, As, Bs);
}

// ---- res GEMM: RESULT += CTX @ w3[:, :512]^T : grid (8, KS) ----
__global__ void __launch_bounds__(256) k_res(const float* __restrict__ w3) {
    __shared__ float As[32][65];
    __shared__ float Bs[32][65];
    gemm_bt_tile<2, true>(g_scr + OFF_CTX, Hc, w3, 1024,
                          g_scr + OFF_RESULT, Hc, nullptr, false,
                          blockIdx.x * 64, blockIdx.y * 64, As, Bs);
}

// ---- gather (with fused beam selection): grid 768, block 512 ----
__global__ void __launch_bounds__(512) k_gather(const int* __restrict__ esi,
                                                const float* __restrict__ prev_scores,
                                                const float* __restrict__ mask,
                                                float* __restrict__ out) {
    __shared__ int ssels[64];
    __shared__ int ssent[64];
    const int t = threadIdx.x;
    const int wb = t >> 5, lane = t & 31;   // 16 warps = 16 batches

    {
        float v = (lane < 16) ? g_scr[OFF_TKLOG + wb * 16 + lane] : INFINITY;
        int rank = 0;
#pragma unroll
        for (int j = 0; j < 16; j++) {
            float vj = __shfl_sync(0xffffffffu, v, j);
            rank += (vj < v) || (vj == v && j < lane);
        }
        if (lane < 16 && rank < 4) {
            int k = wb * 4 + rank;
            int s = wb * 4 + (lane >> 2);
            int rr = lane & 3;
            int sent = g_tkidx[s * 4 + rr];
            ssels[k] = s;
            ssent[k] = sent;
            if (blockIdx.x == 0) {
                out[O_SCORES + k] = v;
                out[O_IDX + k * 4 + 0] = (float)esi[s * 3 + 0];
                out[O_IDX + k * 4 + 1] = (float)esi[s * 3 + 1];
                out[O_IDX + k * 4 + 2] = (float)esi[s * 3 + 2];
                out[O_IDX + k * 4 + 3] = (float)sent;
            }
        }
    }
    __syncthreads();

    int i = blockIdx.x * 512 + t;   // 768*512 = 393216 exact
    if (i < 32768) {
        int bi = i >> 9, j = i & 511;
        out[O_RESULT + i] = g_scr[OFF_RESULT + ssels[bi] * 512 + j];
    } else if (i < 65536) {
        int j = i - 32768;
        out[O_HIDDEN + j] = g_scr[OFF_HNEW + ssels[j >> 9] * 512 + (j & 511)];
    } else if (i < 327680) {
        int j = i - 65536;
        int p = j >> 16;
        int rem = j & 65535;
        int bi = rem >> 10, scol = rem & 1023;
        int s = ssels[bi];
        float v = (p < 3) ? prev_scores[p * 65536 + s * 1024 + scol]
                          : g_scr[OFF_ATTN + s * 1024 + scol];
        out[O_ATTNS + j] = v;
    } else {
        int j = i - 327680;
        int bi = j >> 10, scol = j & 1023;
        int s = ssels[bi];
        float v = (scol == ssent[bi]) ? NEG_INF_VAL : mask[s * 1024 + scol];
        out[O_MASK + j] = v;
    }
}

// ---------------- launch ----------------
extern "C" void kernel_launch(void* const* d_in, const int* in_sizes, int n_in,
                              void* d_out, int out_size) {
    const float* last_hidden = (const float*)d_in[0];
    const float* dec_inputs  = (const float*)d_in[1];
    const float* enc         = (const float*)d_in[2];
    const float* prev_scores = (const float*)d_in[3];
    const float* mask        = (const float*)d_in[4];
    const float* evid        = (const float*)d_in[5];
    const int*   esi         = (const int*)d_in[6];
    const float* w1  = (const float*)d_in[7];
    const float* b1  = (const float*)d_in[8];
    const float* w2  = (const float*)d_in[9];
    const float* b2  = (const float*)d_in[10];
    const float* w3  = (const float*)d_in[11];
    const float* b3  = (const float*)d_in[12];
    const float* wih = (const float*)d_in[13];
    const float* whh = (const float*)d_in[14];
    const float* bih = (const float*)d_in[15];
    const float* bhh = (const float*)d_in[16];
    float* out = (float*)d_out;

    k_gru<<<dim3(24, KS, 2), 256>>>(dec_inputs, last_hidden, wih, whh);
    k_gate<<<64, 512>>>(last_hidden, bih, bhh, b1);
    k_q2<<<dim3(8, KS, 2), 256>>>(w1, w3, b3);
    k_attn<<<1024, 256>>>(enc, mask, evid);
    k_ctx<<<dim3(8, KS), 256>>>(w2, b2);
    k_res<<<dim3(8, KS), 256>>>(w3);
    k_gather<<<768, 512>>>(esi, prev_scores, mask, out);
}

// round 14
// speedup vs baseline: 1.2598x; 1.1048x over previous
#include <cuda_runtime.h>
#include <math.h>

#define NEG_INF_VAL -10000000000.0f

namespace {
constexpr int Hc = 512;
constexpr int Sc = 1024;
constexpr int KS = 8;          // split-K for H=512 GEMMs
constexpr int SLICES = 16;     // attn slices per beam
constexpr int NPART = 64 * SLICES;  // 1024

// float scratch offsets
constexpr int OFF_GIP     = 0;                          // KS*64*1536
constexpr int OFF_GHP     = OFF_GIP + KS * 64 * 1536;
constexpr int OFF_QP      = OFF_GHP + KS * 64 * 1536;   // 64*512 (atomic-accumulated)
constexpr int OFF_HNEW    = OFF_QP + 64 * 512;
constexpr int OFF_QB1     = OFF_HNEW + 64 * 512;
constexpr int OFF_ATTN    = OFF_QB1 + 64;               // 64x1024
constexpr int OFF_PARTM   = OFF_ATTN + 64 * 1024;
constexpr int OFF_PARTL   = OFF_PARTM + NPART;
constexpr int OFF_PARTACC = OFF_PARTL + NPART;          // 1024*512
constexpr int OFF_CTXRAW  = OFF_PARTACC + NPART * 512;
constexpr int OFF_CTX     = OFF_CTXRAW + 64 * 512;
constexpr int OFF_RESULT  = OFF_CTX + 64 * 512;
constexpr int OFF_TKLOG   = OFF_RESULT + 64 * 512;
constexpr int SCR_TOTAL   = OFF_TKLOG + 256;

// output layout (floats), tuple members concatenated in order
constexpr int O_RESULT = 0;
constexpr int O_HIDDEN = 32768;
constexpr int O_IDX    = 65536;
constexpr int O_ATTNS  = 65792;
constexpr int O_MASK   = 327936;
constexpr int O_SCORES = 393472;
}

__device__ __align__(16) float g_scr[SCR_TOTAL];
__device__ int g_tkidx[256];

// wait for the programmatically-linked predecessor kernel to fully complete
__device__ __forceinline__ void dep_sync() {
#if __CUDA_ARCH__ >= 900
    cudaGridDependencySynchronize();
#endif
}

// ---------------- GEMM tiles (64 rows x 64 cols, K-chunk = ITERS*32) ----------------
template<int ITERS, bool ATOMIC>
__device__ __forceinline__ void gemm_bt_tile(const float* __restrict__ A, int lda,
                                             const float* __restrict__ B, int ldb,
                                             float* __restrict__ C, int ldc,
                                             const float* __restrict__ bias, bool addBias,
                                             int j0, int k0,
                                             float (*As)[65], float (*Bs)[65]) {
    const int t = threadIdx.x;
    const int bx = (t & 15) * 4;
    const int by = (t >> 4) * 4;
    float acc[4][4] = {};
#pragma unroll
    for (int it = 0; it < ITERS; it++) {
        const int kk = k0 + it * 32;
#pragma unroll
        for (int i = 0; i < 8; i++) {
            int idx = t + i * 256;
            int r = idx >> 5, c = idx & 31;
            As[c][r] = A[r * lda + kk + c];
            Bs[c][r] = B[(j0 + r) * ldb + kk + c];
        }
        __syncthreads();
#pragma unroll
        for (int c = 0; c < 32; c++) {
            float b0 = Bs[c][bx + 0], b1 = Bs[c][bx + 1], b2 = Bs[c][bx + 2], b3 = Bs[c][bx + 3];
#pragma unroll
            for (int r = 0; r < 4; r++) {
                float av = As[c][by + r];
                acc[r][0] += av * b0; acc[r][1] += av * b1;
                acc[r][2] += av * b2; acc[r][3] += av * b3;
            }
        }
        __syncthreads();
    }
#pragma unroll
    for (int r = 0; r < 4; r++)
#pragma unroll
        for (int cc = 0; cc < 4; cc++) {
            float v = acc[r][cc];
            if (addBias) v += bias[j0 + bx + cc];
            if (ATOMIC) atomicAdd(&C[(by + r) * ldc + j0 + bx + cc], v);
            else        C[(by + r) * ldc + j0 + bx + cc] = v;
        }
}

template<int ITERS, bool ATOMIC>
__device__ __forceinline__ void gemm_ab_tile(const float* __restrict__ A, int lda,
                                             const float* __restrict__ B, int ldb,
                                             float* __restrict__ C, int ldc,
                                             int j0, int k0,
                                             float (*As)[65], float (*Bs)[65]) {
    const int t = threadIdx.x;
    const int bx = (t & 15) * 4;
    const int by = (t >> 4) * 4;
    float acc[4][4] = {};
#pragma unroll
    for (int it = 0; it < ITERS; it++) {
        const int kk = k0 + it * 32;
#pragma unroll
        for (int i = 0; i < 8; i++) {
            int idx = t + i * 256;
            int r = idx >> 5, c = idx & 31;
            As[c][r] = A[r * lda + kk + c];
        }
#pragma unroll
        for (int i = 0; i < 8; i++) {
            int idx = t + i * 256;
            int c = idx >> 6, jj = idx & 63;
            Bs[c][jj] = B[(kk + c) * ldb + j0 + jj];
        }
        __syncthreads();
#pragma unroll
        for (int c = 0; c < 32; c++) {
            float b0 = Bs[c][bx + 0], b1 = Bs[c][bx + 1], b2 = Bs[c][bx + 2], b3 = Bs[c][bx + 3];
#pragma unroll
            for (int r = 0; r < 4; r++) {
                float av = As[c][by + r];
                acc[r][0] += av * b0; acc[r][1] += av * b1;
                acc[r][2] += av * b2; acc[r][3] += av * b3;
            }
        }
        __syncthreads();
    }
#pragma unroll
    for (int r = 0; r < 4; r++)
#pragma unroll
        for (int cc = 0; cc < 4; cc++) {
            if (ATOMIC) atomicAdd(&C[(by + r) * ldc + j0 + bx + cc], acc[r][cc]);
            else        C[(by + r) * ldc + j0 + bx + cc] = acc[r][cc];
        }
}

// ---- gi/gh partials: grid (24, KS, 2), block 256 ----
__global__ void __launch_bounds__(256) k_gru(const float* __restrict__ x, const float* __restrict__ h,
                                             const float* __restrict__ wih, const float* __restrict__ whh) {
    __shared__ float As[32][65];
    __shared__ float Bs[32][65];
    const float* A = blockIdx.z ? h : x;
    const float* B = blockIdx.z ? whh : wih;
    float* C = g_scr + (blockIdx.z ? OFF_GHP : OFF_GIP) + blockIdx.y * (64 * 1536);
    gemm_bt_tile<2, false>(A, Hc, B, Hc, C, 1536, nullptr, false,
                           blockIdx.x * 64, blockIdx.y * 64, As, Bs);
}

// ---- GRU gates + qb1 + zero RESULT/QP: grid 64, block 512 ----
__global__ void __launch_bounds__(512) k_gate(const float* __restrict__ lh, const float* __restrict__ bih,
                                              const float* __restrict__ bhh, const float* __restrict__ b1) {
    int b = blockIdx.x, j = threadIdx.x;
    dep_sync();   // wait for k_gru partials
    float gir = bih[j],        ghr = bhh[j];
    float giz = bih[512 + j],  ghz = bhh[512 + j];
    float gin = bih[1024 + j], ghn = bhh[1024 + j];
#pragma unroll
    for (int p = 0; p < KS; p++) {
        const float* gi = g_scr + OFF_GIP + p * (64 * 1536) + b * 1536;
        const float* gh = g_scr + OFF_GHP + p * (64 * 1536) + b * 1536;
        gir += gi[j];        ghr += gh[j];
        giz += gi[512 + j];  ghz += gh[512 + j];
        gin += gi[1024 + j]; ghn += gh[1024 + j];
    }
    float r = 1.f / (1.f + expf(-(gir + ghr)));
    float z = 1.f / (1.f + expf(-(giz + ghz)));
    float n = tanhf(gin + r * ghn);
    float hv = lh[b * Hc + j];
    float hn = (1.f - z) * n + z * hv;
    g_scr[OFF_HNEW + b * Hc + j] = hn;
    g_scr[OFF_RESULT + b * Hc + j] = 0.f;   // zero accumulator for result adds
    g_scr[OFF_QP + b * Hc + j] = 0.f;       // zero accumulator for q atomics

    float p = hn * b1[j];
    __shared__ float red[16];
#pragma unroll
    for (int o = 16; o; o >>= 1) p += __shfl_xor_sync(0xffffffffu, p, o);
    if ((j & 31) == 0) red[j >> 5] = p;
    __syncthreads();
    if (j < 16) {
        float v = red[j];
#pragma unroll
        for (int o = 8; o; o >>= 1) v += __shfl_xor_sync(0x0000ffffu, v, o);
        if (j == 0) g_scr[OFF_QB1 + b] = v;
    }
}

// ---- q (z=0, atomic into QP) + RESULT += hnew @ w3[:,512:]^T + b3 (z=1): grid (8, KS, 2) ----
__global__ void __launch_bounds__(256) k_q2(const float* __restrict__ w1,
                                            const float* __restrict__ w3,
                                            const float* __restrict__ b3) {
    __shared__ float As[32][65];
    __shared__ float Bs[32][65];
    dep_sync();   // wait for k_gate (HNEW + zeroed QP/RESULT)
    if (blockIdx.z == 0) {
        gemm_ab_tile<2, true>(g_scr + OFF_HNEW, Hc, w1, Hc,
                              g_scr + OFF_QP, Hc,
                              blockIdx.x * 64, blockIdx.y * 64, As, Bs);
    } else {
        gemm_bt_tile<2, true>(g_scr + OFF_HNEW, Hc, w3 + 512, 1024,
                              g_scr + OFF_RESULT, Hc, b3, blockIdx.y == 0,
                              blockIdx.x * 64, blockIdx.y * 64, As, Bs);
    }
}

// ================= ATTN: streaming score + online softmax + context ===========
// grid 1024 (16 slices/beam), block 256, 64 rows/block in 16 chunks of 4 rows.
// smem ~18.6KB, regs capped for 8 blocks/SM -> all 1024 blocks in ONE wave.
__device__ __forceinline__ void cp_prefetch4(float4* dst, const float4* src, int t) {
#pragma unroll
    for (int i = 0; i < 2; i++) {
        unsigned d = (unsigned)__cvta_generic_to_shared(dst + t + i * 256);
        asm volatile("cp.async.cg.shared.global [%0], [%1], 16;\n" :: "r"(d), "l"(src + t + i * 256));
    }
    asm volatile("cp.async.commit_group;\n");
}

__global__ void __launch_bounds__(256, 8) k_attn(const float* __restrict__ enc,
                                                 const float* __restrict__ mask) {
    constexpr float inv_div = 0.04419417382415922f;  // 1/sqrt(512)
    __shared__ float qs[512];
    __shared__ float4 buf[2][512];   // 2 x (4 rows x 512 f32) = 16KB
    __shared__ float scs[4];
    __shared__ float ws[4];
    __shared__ float smask[64];

    const int t = threadIdx.x;
    const int b = blockIdx.x >> 4;
    const int slice = blockIdx.x & 15;
    const int sbase = slice * 64;
    const float* encb = enc + (size_t)b * Sc * Hc;

    // first chunk prefetch + mask staging touch only kernel inputs — issue before the dep wait
    cp_prefetch4(buf[0], reinterpret_cast<const float4*>(encb + (size_t)sbase * Hc), t);
    if (t < 64) smask[t] = mask[b * Sc + sbase + t];

    dep_sync();   // wait for k_q2 (QP, QB1)

    qs[t]       = g_scr[OFF_QP + b * Hc + t] * inv_div;
    qs[t + 256] = g_scr[OFF_QP + b * Hc + t + 256] * inv_div;
    const float cb = g_scr[OFF_QB1 + b] * inv_div;

    const int w = t >> 5, lane = t & 31;
    float m = -INFINITY, l = 0.f, a0 = 0.f, a1 = 0.f;

    for (int c = 0; c < 16; c++) {
        asm volatile("cp.async.wait_group 0;\n");
        __syncthreads();   // chunk c ready AND all threads done with buf[(c+1)&1]

        if (c < 15)
            cp_prefetch4(buf[(c + 1) & 1],
                         reinterpret_cast<const float4*>(encb + (size_t)(sbase + (c + 1) * 4) * Hc), t);

        const float* ch = reinterpret_cast<const float*>(buf[c & 1]);
        const int s0 = sbase + c * 4;

        // scores: warps 0-3 each compute one row
        if (w < 4) {
            float d = 0.f;
#pragma unroll
            for (int kk = 0; kk < 16; kk++) {
                int k = lane + kk * 32;
                d += ch[w * 512 + k] * qs[k];
            }
#pragma unroll
            for (int o = 16; o; o >>= 1) d += __shfl_xor_sync(0xffffffffu, d, o);
            if (lane == 0) {
                float sc = d + cb + smask[c * 4 + w];
                scs[w] = sc;
                g_scr[OFF_ATTN + b * Sc + s0 + w] = sc;
            }
        }
        __syncthreads();

        float cm = fmaxf(fmaxf(scs[0], scs[1]), fmaxf(scs[2], scs[3]));
        float nm = fmaxf(m, cm);
        if (nm > m) {
            float scale = expf(m - nm);
            a0 *= scale; a1 *= scale; l *= scale;
        }
        if (t < 4) ws[t] = expf(scs[t] - nm);
        __syncthreads();

        float lsum = 0.f;
#pragma unroll
        for (int r = 0; r < 4; r++) {
            float wr = ws[r];
            lsum += wr;
            a0 += wr * ch[r * 512 + t];
            a1 += wr * ch[r * 512 + t + 256];
        }
        l += lsum;
        m = nm;
        // next iteration's first sync protects ch/ws/scs
    }
    const int pid = blockIdx.x;
    if (t == 0) { g_scr[OFF_PARTM + pid] = m; g_scr[OFF_PARTL + pid] = l; }
    g_scr[OFF_PARTACC + pid * 512 + t]       = a0;
    g_scr[OFF_PARTACC + pid * 512 + t + 256] = a1;
}

// ---- combine partials -> ctxraw, zero CTX, top-4, TKLOG: grid 64, block 256 ----
__global__ void __launch_bounds__(256) k_combine(const float* __restrict__ evid) {
    __shared__ float sv[1024];
    __shared__ int pick[4];
    __shared__ float pickv[4];
    __shared__ float wvv[8];
    __shared__ int wii[8];
    const int b = blockIdx.x, t = threadIdx.x;
    dep_sync();   // wait for k_attn partials

    float pm[SLICES], e[SLICES];
    float M = -INFINITY;
#pragma unroll
    for (int p = 0; p < SLICES; p++) { pm[p] = g_scr[OFF_PARTM + b * SLICES + p]; M = fmaxf(M, pm[p]); }
    float L = 0.f;
#pragma unroll
    for (int p = 0; p < SLICES; p++) { e[p] = expf(pm[p] - M); L += g_scr[OFF_PARTL + b * SLICES + p] * e[p]; }
    float invL = 1.f / L;
#pragma unroll
    for (int half = 0; half < 2; half++) {
        int col = t + half * 256;
        float s = 0.f;
#pragma unroll
        for (int p = 0; p < SLICES; p++)
            s += e[p] * g_scr[OFF_PARTACC + (b * SLICES + p) * 512 + col];
        g_scr[OFF_CTXRAW + b * Hc + col] = s * invL;
        g_scr[OFF_CTX + b * Hc + col] = 0.f;
    }
#pragma unroll
    for (int i = 0; i < 4; i++) sv[t + i * 256] = g_scr[OFF_ATTN + b * Sc + t + i * 256];
    __syncthreads();
    for (int round = 0; round < 4; round++) {
        float best = -INFINITY;
        int bi = 0x7fffffff;
#pragma unroll
        for (int u = 0; u < 4; u++) {
            int idx = t * 4 + u;
            bool skip = false;
            for (int rr = 0; rr < round; rr++) skip |= (pick[rr] == idx);
            float v = sv[idx];
            if (!skip && (v > best || (v == best && idx < bi))) { best = v; bi = idx; }
        }
#pragma unroll
        for (int o = 16; o; o >>= 1) {
            float ov = __shfl_xor_sync(0xffffffffu, best, o);
            int   oi = __shfl_xor_sync(0xffffffffu, bi, o);
            if (ov > best || (ov == best && oi < bi)) { best = ov; bi = oi; }
        }
        if ((t & 31) == 0) { wvv[t >> 5] = best; wii[t >> 5] = bi; }
        __syncthreads();
        if (t == 0) {
            float bb = wvv[0]; int bj = wii[0];
            for (int k = 1; k < 8; k++)
                if (wvv[k] > bb || (wvv[k] == bb && wii[k] < bj)) { bb = wvv[k]; bj = wii[k]; }
            pick[round] = bj; pickv[round] = bb;
        }
        __syncthreads();
    }
    if (t < 4) {
        g_scr[OFF_TKLOG + b * 4 + t] = (M - pickv[t]) + logf(L) + evid[b];
        g_tkidx[b * 4 + t] = pick[t];
    }
}

// ---- ctx GEMM: CTX += ctxraw @ w2^T + b2 : grid (8, KS) ----
__global__ void __launch_bounds__(256) k_ctx(const float* __restrict__ w2, const float* __restrict__ b2) {
    __shared__ float As[32][65];
    __shared__ float Bs[32][65];
    dep_sync();   // wait for k_combine (ctxraw + zeroed CTX)
    gemm_bt_tile<2, true>(g_scr + OFF_CTXRAW, Hc, w2, Hc,
                          g_scr + OFF_CTX, Hc, b2, blockIdx.y == 0,
                          blockIdx.x * 64, blockIdx.y * 64, As, Bs);
}

// ---- res GEMM: RESULT += CTX @ w3[:, :512]^T : grid (8, KS) ----
__global__ void __launch_bounds__(256) k_res(const float* __restrict__ w3) {
    __shared__ float As[32][65];
    __shared__ float Bs[32][65];
    dep_sync();   // wait for k_ctx
    gemm_bt_tile<2, true>(g_scr + OFF_CTX, Hc, w3, 1024,
                          g_scr + OFF_RESULT, Hc, nullptr, false,
                          blockIdx.x * 64, blockIdx.y * 64, As, Bs);
}

// ---- gather (with fused beam selection): grid 768, block 512 ----
__global__ void __launch_bounds__(512) k_gather(const int* __restrict__ esi,
                                                const float* __restrict__ prev_scores,
                                                const float* __restrict__ mask,
                                                float* __restrict__ out) {
    __shared__ int ssels[64];
    __shared__ int ssent[64];
    const int t = threadIdx.x;
    const int wb = t >> 5, lane = t & 31;   // 16 warps = 16 batches
    dep_sync();   // wait for k_res (RESULT complete; TKLOG/ATTN transitively complete)

    {
        float v = (lane < 16) ? g_scr[OFF_TKLOG + wb * 16 + lane] : INFINITY;
        int rank = 0;
#pragma unroll
        for (int j = 0; j < 16; j++) {
            float vj = __shfl_sync(0xffffffffu, v, j);
            rank += (vj < v) || (vj == v && j < lane);
        }
        if (lane < 16 && rank < 4) {
            int k = wb * 4 + rank;
            int s = wb * 4 + (lane >> 2);
            int rr = lane & 3;
            int sent = g_tkidx[s * 4 + rr];
            ssels[k] = s;
            ssent[k] = sent;
            if (blockIdx.x == 0) {
                out[O_SCORES + k] = v;
                out[O_IDX + k * 4 + 0] = (float)esi[s * 3 + 0];
                out[O_IDX + k * 4 + 1] = (float)esi[s * 3 + 1];
                out[O_IDX + k * 4 + 2] = (float)esi[s * 3 + 2];
                out[O_IDX + k * 4 + 3] = (float)sent;
            }
        }
    }
    __syncthreads();

    int i = blockIdx.x * 512 + t;   // 768*512 = 393216 exact
    if (i < 32768) {
        int bi = i >> 9, j = i & 511;
        out[O_RESULT + i] = g_scr[OFF_RESULT + ssels[bi] * 512 + j];
    } else if (i < 65536) {
        int j = i - 32768;
        out[O_HIDDEN + j] = g_scr[OFF_HNEW + ssels[j >> 9] * 512 + (j & 511)];
    } else if (i < 327680) {
        int j = i - 65536;
        int p = j >> 16;
        int rem = j & 65535;
        int bi = rem >> 10, scol = rem & 1023;
        int s = ssels[bi];
        float v = (p < 3) ? prev_scores[p * 65536 + s * 1024 + scol]
                          : g_scr[OFF_ATTN + s * 1024 + scol];
        out[O_ATTNS + j] = v;
    } else {
        int j = i - 327680;
        int bi = j >> 10, scol = j & 1023;
        int s = ssels[bi];
        float v = (scol == ssent[bi]) ? NEG_INF_VAL : mask[s * 1024 + scol];
        out[O_MASK + j] = v;
    }
}

// ---------------- launch helpers ----------------
static inline void launch_pdl(const void* func, dim3 grid, dim3 block, void** args) {
    cudaLaunchConfig_t cfg = {};
    cfg.gridDim = grid;
    cfg.blockDim = block;
    cfg.dynamicSmemBytes = 0;
    cfg.stream = 0;
    cudaLaunchAttribute attr[1];
    attr[0].id = cudaLaunchAttributeProgrammaticStreamSerialization;
    attr[0].val.programmaticStreamSerializationAllowed = 1;
    cfg.attrs = attr;
    cfg.numAttrs = 1;
    cudaLaunchKernelExC(&cfg, func, args);
}

extern "C" void kernel_launch(void* const* d_in, const int* in_sizes, int n_in,
                              void* d_out, int out_size) {
    const float* last_hidden = (const float*)d_in[0];
    const float* dec_inputs  = (const float*)d_in[1];
    const float* enc         = (const float*)d_in[2];
    const float* prev_scores = (const float*)d_in[3];
    const float* mask        = (const float*)d_in[4];
    const float* evid        = (const float*)d_in[5];
    const int*   esi         = (const int*)d_in[6];
    const float* w1  = (const float*)d_in[7];
    const float* b1  = (const float*)d_in[8];
    const float* w2  = (const float*)d_in[9];
    const float* b2  = (const float*)d_in[10];
    const float* w3  = (const float*)d_in[11];
    const float* b3  = (const float*)d_in[12];
    const float* wih = (const float*)d_in[13];
    const float* whh = (const float*)d_in[14];
    const float* bih = (const float*)d_in[15];
    const float* bhh = (const float*)d_in[16];
    float* out = (float*)d_out;

    k_gru<<<dim3(24, KS, 2), 256>>>(dec_inputs, last_hidden, wih, whh);

    { void* a[] = {(void*)&last_hidden, (void*)&bih, (void*)&bhh, (void*)&b1};
      launch_pdl((const void*)k_gate, dim3(64), dim3(512), a); }
    { void* a[] = {(void*)&w1, (void*)&w3, (void*)&b3};
      launch_pdl((const void*)k_q2, dim3(8, KS, 2), dim3(256), a); }
    { void* a[] = {(void*)&enc, (void*)&mask};
      launch_pdl((const void*)k_attn, dim3(1024), dim3(256), a); }
    { void* a[] = {(void*)&evid};
      launch_pdl((const void*)k_combine, dim3(64), dim3(256), a); }
    { void* a[] = {(void*)&w2, (void*)&b2};
      launch_pdl((const void*)k_ctx, dim3(8, KS), dim3(256), a); }
    { void* a[] = {(void*)&w3};
      launch_pdl((const void*)k_res, dim3(8, KS), dim3(256), a); }
    { void* a[] = {(void*)&esi, (void*)&prev_scores, (void*)&mask, (void*)&out};
      launch_pdl((const void*)k_gather, dim3(768), dim3(512), a); }
}